// round 14
// baseline (speedup 1.0000x reference)
#include <cuda_runtime.h>
#include <cuda_fp16.h>
#include <math_constants.h>
#include <cstdint>

#define NTOK 4096
#define CDIM 1024
#define BM 64
#define BN 128
#define BK 32
#define LDS_A 40    // K-major tile row stride (fp16): 80B, conflict-free ldmatrix
#define LDS_B 136   // trans-B tile row stride (fp16): 272B, conflict-free ldmatrix.trans
#define NTHR 128    // 4 warps, 2x2 of 32x64

// ---------------------------------------------------------------------------
// Scratch (__device__ globals; allocation-free rule)
// ---------------------------------------------------------------------------
__device__ __half g_xh[(size_t)NTOK * CDIM];
__device__ __half g_Wq[(size_t)CDIM * CDIM];
__device__ __half g_Wk[(size_t)CDIM * CDIM];
__device__ __half g_Wv[(size_t)CDIM * CDIM];
__device__ __half g_Wo[(size_t)CDIM * CDIM];
__device__ __half g_Q[(size_t)NTOK * CDIM];
__device__ __half g_K[(size_t)NTOK * CDIM];
__device__ __half g_V[(size_t)NTOK * CDIM];
__device__ float  g_S[(size_t)NTOK * NTOK];
__device__ __half g_P[(size_t)NTOK * NTOK];
__device__ float  g_Hp[4ULL * NTOK * CDIM];   // PV split-K partials (fp32)
__device__ __half g_H[(size_t)NTOK * CDIM];

// dependency counters (reset by the convert kernel each call); 64 m-blocks of 64 rows
__device__ int g_cnt[512];
#define C_QDONE 0     // 64 ctrs, target 8   (per Q 64-row block)
#define C_KDONE 64    // 64 ctrs, target 8   (per K 64-row block)
#define C_SCNT  128   // 64 ctrs, target 32  (per S m-block, 32 n-tiles)
#define C_PDONE 192   // 64 ctrs, target 4   (per m-block softmax chunks of 16 rows)
#define C_HRDY  256   // 64 ctrs, target 32  (per m-block PV tiles: 8 nb x 4 ks)
#define C_RDONE 320   // 64 ctrs, target 4   (per m-block reduce chunks)
#define C_VKS   384   // 4 ctrs,  target 128 (V proj tiles per 1024-row quarter)

// ---------------------------------------------------------------------------
// PTX helpers (sm_80-compatible only: cp.async / ldmatrix / mma.sync)
// ---------------------------------------------------------------------------
__device__ __forceinline__ uint32_t smem_u32(const void* p) {
    uint32_t a;
    asm("{ .reg .u64 t; cvta.to.shared.u64 t, %1; cvt.u32.u64 %0, t; }" : "=r"(a) : "l"(p));
    return a;
}

__device__ __forceinline__ void cpa16(uint32_t dst, const __half* src) {
    asm volatile("cp.async.cg.shared.global [%0], [%1], 16;" :: "r"(dst), "l"(src));
}
#define CP_COMMIT() asm volatile("cp.async.commit_group;")
#define CP_WAIT(n)  asm volatile("cp.async.wait_group %0;" :: "n"(n))

#define LDMX4(r, addr) \
    asm volatile("ldmatrix.sync.aligned.m8n8.x4.shared.b16 {%0,%1,%2,%3}, [%4];" \
                 : "=r"((r)[0]), "=r"((r)[1]), "=r"((r)[2]), "=r"((r)[3]) : "r"(addr))

#define LDMX4T(r, addr) \
    asm volatile("ldmatrix.sync.aligned.m8n8.x4.trans.shared.b16 {%0,%1,%2,%3}, [%4];" \
                 : "=r"((r)[0]), "=r"((r)[1]), "=r"((r)[2]), "=r"((r)[3]) : "r"(addr))

__device__ __forceinline__ void mma16816(float* c, const uint32_t* a, const uint32_t* b) {
    asm volatile(
        "mma.sync.aligned.m16n8k16.row.col.f32.f16.f16.f32 "
        "{%0,%1,%2,%3}, {%4,%5,%6,%7}, {%8,%9}, {%0,%1,%2,%3};"
        : "+f"(c[0]), "+f"(c[1]), "+f"(c[2]), "+f"(c[3])
        : "r"(a[0]), "r"(a[1]), "r"(a[2]), "r"(a[3]), "r"(b[0]), "r"(b[1]));
}

// ---------------------------------------------------------------------------
// sync helpers for the in-kernel DAG
// ---------------------------------------------------------------------------
__device__ __forceinline__ void spin_ge(int idx, int target) {
    volatile int* p = (volatile int*)&g_cnt[idx];
    if (threadIdx.x == 0) {
        while (*p < target) __nanosleep(128);
    }
    __syncthreads();
}
__device__ __forceinline__ void signal(int idx) {
    __threadfence();
    __syncthreads();
    if (threadIdx.x == 0) atomicAdd(&g_cnt[idx], 1);
}

// ---------------------------------------------------------------------------
// smem layout: A slot (64x32 K-major, 5120B) + B slot (128x32 K-major 10240B
// OR 32x128 trans 8704B)
// ---------------------------------------------------------------------------
#define SLOT_A 5120
#define SLOT_B 10240
#define STAGE_B (SLOT_A + SLOT_B)          // 15360
#define NSTAGE 3
#define SMEM_TOTAL (NSTAGE * STAGE_B)      // 46080  (4 CTAs/SM -> 184KB)

// K-major tile loader: ROWS rows x 32 k; 128 threads
template <int ROWS>
__device__ __forceinline__ void load_km(uint32_t sbase, const __half* __restrict__ g,
                                        int row0, int stride, int kcol, int t) {
#pragma unroll
    for (int i = 0; i < ROWS / 32; ++i) {
        int id = t + i * NTHR;
        int row = id >> 2, q = id & 3;
        cpa16(sbase + (uint32_t)(row * LDS_A + q * 8) * 2,
              g + (size_t)(row0 + row) * stride + kcol + q * 8);
    }
}

// trans-B tile loader: 32 rows (k) x 128 halves (n), n contiguous (stride CDIM)
__device__ __forceinline__ void load_bt(uint32_t sbase, const __half* __restrict__ g,
                                        int n0, int kc, int t) {
#pragma unroll
    for (int i = 0; i < 4; ++i) {
        int id = t + i * NTHR;         // 0..511
        int row = id >> 4;             // 0..31 (k)
        int q = id & 15;               // 16B chunk within 256B row
        cpa16(sbase + (uint32_t)(row * LDS_B + q * 8) * 2,
              g + (size_t)(kc + row) * CDIM + n0 + q * 8);
    }
}

// ---------------------------------------------------------------------------
// GEMM tile body: D[64,128] = A[m0.., :Klen] @ B^T
// BT: 0 = B K-major [n][k], 1 = B row-major [k][n] via ldmatrix.trans
// EPI: 0 = fp16 out + bias, 1 = fp32 out, 2 = fp32 out + bias + resid
// 4 warps in 2x2, warp tile 32x64
// ---------------------------------------------------------------------------
template <int BT, int EPI>
__device__ __forceinline__ void gemm_body(
    const __half* __restrict__ Ah, const __half* __restrict__ Bg,
    const float* __restrict__ bias, const float* __restrict__ resid,
    __half* __restrict__ oh, float* __restrict__ of,
    int Klen, int Astride, int Bstride, int Nout, int m0, int n0, uint32_t sb)
{
    const int t = threadIdx.x;
    const int lane = t & 31;
    const int wid = t >> 5;            // 0..3
    const int nch = Klen / BK;

    const int warp_m = (wid & 1) * 32;
    const int warp_n = (wid >> 1) * 64;

    const uint32_t aoff = (uint32_t)((warp_m + (lane & 15)) * LDS_A + (lane >> 4) * 8) * 2;
    const uint32_t boff = (uint32_t)((warp_n + ((lane >> 4) & 1) * 8 + (lane & 7)) * LDS_A
                                     + ((lane >> 3) & 1) * 8) * 2;
    const uint32_t boffT = (uint32_t)(((((lane >> 3) & 1) * 8 + (lane & 7)) * LDS_B)
                                      + warp_n + (lane >> 4) * 8) * 2;

    float acc[2][8][4];
#pragma unroll
    for (int i = 0; i < 2; ++i)
#pragma unroll
        for (int j = 0; j < 8; ++j)
#pragma unroll
            for (int r = 0; r < 4; ++r) acc[i][j][r] = 0.0f;

#pragma unroll
    for (int s = 0; s < 2; ++s) {
        uint32_t sg = sb + s * STAGE_B;
        int kc = s * BK;
        load_km<BM>(sg, Ah, m0, Astride, kc, t);
        if (BT) load_bt(sg + SLOT_A, Bg, n0, kc, t);
        else    load_km<BN>(sg + SLOT_A, Bg, n0, Bstride, kc, t);
        CP_COMMIT();
    }

    int slot = 0, slot2 = 2;
    for (int c = 0; c < nch; ++c) {
        if (c + 1 < nch) { CP_WAIT(1); } else { CP_WAIT(0); }
        __syncthreads();

        if (c + 2 < nch) {
            uint32_t sg = sb + slot2 * STAGE_B;
            int kc = (c + 2) * BK;
            load_km<BM>(sg, Ah, m0, Astride, kc, t);
            if (BT) load_bt(sg + SLOT_A, Bg, n0, kc, t);
            else    load_km<BN>(sg + SLOT_A, Bg, n0, Bstride, kc, t);
            CP_COMMIT();
        }

        const uint32_t s0 = sb + slot * STAGE_B;
#pragma unroll
        for (int s = 0; s < 2; ++s) {
            uint32_t ah[2][4], bh[8][2];
#pragma unroll
            for (int i = 0; i < 2; ++i) {
                const uint32_t ao = (uint32_t)(i * 16 * LDS_A + s * 16) * 2;
                LDMX4(ah[i], s0 + aoff + ao);
            }
#pragma unroll
            for (int g = 0; g < 4; ++g) {
                uint32_t r[4];
                if (BT) {
                    const uint32_t bo = (uint32_t)(s * 16 * LDS_B + g * 16) * 2;
                    LDMX4T(r, s0 + SLOT_A + boffT + bo);
                } else {
                    const uint32_t bo = (uint32_t)(g * 16 * LDS_A + s * 16) * 2;
                    LDMX4(r, s0 + SLOT_A + boff + bo);
                }
                bh[2 * g][0] = r[0]; bh[2 * g][1] = r[1];
                bh[2 * g + 1][0] = r[2]; bh[2 * g + 1][1] = r[3];
            }
#pragma unroll
            for (int i = 0; i < 2; ++i)
#pragma unroll
                for (int j = 0; j < 8; ++j)
                    mma16816(acc[i][j], ah[i], bh[j]);
        }
        slot = (slot + 1 == NSTAGE) ? 0 : slot + 1;
        slot2 = (slot2 + 1 == NSTAGE) ? 0 : slot2 + 1;
    }

    // epilogue
#pragma unroll
    for (int i = 0; i < 2; ++i) {
        const int r0 = m0 + warp_m + i * 16 + (lane >> 2);
        const int r1 = r0 + 8;
#pragma unroll
        for (int j = 0; j < 8; ++j) {
            const int cc = n0 + warp_n + j * 8 + (lane & 3) * 2;
            float v0 = acc[i][j][0], v1 = acc[i][j][1];
            float v2 = acc[i][j][2], v3 = acc[i][j][3];

            if (EPI == 1) {
                *(float2*)(of + (size_t)r0 * Nout + cc) = make_float2(v0, v1);
                *(float2*)(of + (size_t)r1 * Nout + cc) = make_float2(v2, v3);
            } else if (EPI == 2) {
                const float b0 = bias[cc], b1 = bias[cc + 1];
                float2 ra = *(const float2*)(resid + (size_t)r0 * Nout + cc);
                float2 rb = *(const float2*)(resid + (size_t)r1 * Nout + cc);
                *(float2*)(of + (size_t)r0 * Nout + cc) = make_float2(v0 + b0 + ra.x, v1 + b1 + ra.y);
                *(float2*)(of + (size_t)r1 * Nout + cc) = make_float2(v2 + b0 + rb.x, v3 + b1 + rb.y);
            } else {
                const float b0 = bias[cc], b1 = bias[cc + 1];
                v0 += b0; v1 += b1; v2 += b0; v3 += b1;
                *(__half2*)(oh + (size_t)r0 * Nout + cc) =
                    __halves2half2(__float2half_rn(v0), __float2half_rn(v1));
                *(__half2*)(oh + (size_t)r1 * Nout + cc) =
                    __halves2half2(__float2half_rn(v2), __float2half_rn(v3));
            }
        }
    }
}

// ---------------------------------------------------------------------------
// softmax body: 16 rows, 128 threads, fp32 S -> fp16 P
// ---------------------------------------------------------------------------
__device__ __forceinline__ float warpMax(float v) {
#pragma unroll
    for (int o = 16; o > 0; o >>= 1) v = fmaxf(v, __shfl_xor_sync(0xffffffffu, v, o));
    return v;
}
__device__ __forceinline__ float warpSum(float v) {
#pragma unroll
    for (int o = 16; o > 0; o >>= 1) v += __shfl_xor_sync(0xffffffffu, v, o);
    return v;
}

__device__ void softmax_body(const float* __restrict__ S, __half* __restrict__ P,
                             int row0, char* smemraw) {
    float* red = (float*)smemraw;
    const int t = threadIdx.x;
    const int lane = t & 31, wid = t >> 5;

    for (int r = 0; r < 16; ++r) {
        const int row = row0 + r;
        const float4* pr = (const float4*)(S + (size_t)row * NTOK);
        float4 v[8];
#pragma unroll
        for (int i = 0; i < 8; ++i) v[i] = pr[t + NTHR * i];

        float m = -CUDART_INF_F;
#pragma unroll
        for (int i = 0; i < 8; ++i)
            m = fmaxf(m, fmaxf(fmaxf(v[i].x, v[i].y), fmaxf(v[i].z, v[i].w)));
        m = warpMax(m);
        if (lane == 0) red[wid] = m;
        __syncthreads();
        if (t < 32) {
            float z = (t < 4) ? red[t] : -CUDART_INF_F;
            z = warpMax(z);
            if (t == 0) red[4] = z;
        }
        __syncthreads();
        m = red[4];

        float s = 0.0f;
#pragma unroll
        for (int i = 0; i < 8; ++i) {
            v[i].x = __expf(v[i].x - m); v[i].y = __expf(v[i].y - m);
            v[i].z = __expf(v[i].z - m); v[i].w = __expf(v[i].w - m);
            s += (v[i].x + v[i].y) + (v[i].z + v[i].w);
        }
        s = warpSum(s);
        __syncthreads();
        if (lane == 0) red[wid] = s;
        __syncthreads();
        if (t < 32) {
            float z = (t < 4) ? red[t] : 0.0f;
            z = warpSum(z);
            if (t == 0) red[4] = z;
        }
        __syncthreads();
        const float inv = 1.0f / red[4];

        uint2* po = (uint2*)(P + (size_t)row * NTOK);
#pragma unroll
        for (int i = 0; i < 8; ++i) {
            __half2 h0 = __floats2half2_rn(v[i].x * inv, v[i].y * inv);
            __half2 h1 = __floats2half2_rn(v[i].z * inv, v[i].w * inv);
            uint2 u;
            u.x = *(uint32_t*)&h0;
            u.y = *(uint32_t*)&h1;
            po[t + NTHR * i] = u;
        }
        __syncthreads();
    }
}

// ---------------------------------------------------------------------------
// H reduce body: H = sum of 4 fp32 partials -> fp16.  16 rows, 128 threads.
// ---------------------------------------------------------------------------
__device__ void reduce_body(const float* __restrict__ Hp, __half* __restrict__ H, int row0) {
    const int t = threadIdx.x;
    const size_t plane = (size_t)NTOK * CDIM;
    for (int r = 0; r < 16; ++r) {
        const int row = row0 + r;
#pragma unroll
        for (int i = 0; i < 2; ++i) {
            const int col = t + i * NTHR;
            const float4* h0 = (const float4*)(Hp + (size_t)row * CDIM);
            const float4* h1 = (const float4*)(Hp + plane + (size_t)row * CDIM);
            const float4* h2 = (const float4*)(Hp + 2 * plane + (size_t)row * CDIM);
            const float4* h3 = (const float4*)(Hp + 3 * plane + (size_t)row * CDIM);
            float4 a = h0[col], b = h1[col], c = h2[col], d = h3[col];
            __half2 p0 = __floats2half2_rn(a.x + b.x + c.x + d.x, a.y + b.y + c.y + d.y);
            __half2 p1 = __floats2half2_rn(a.z + b.z + c.z + d.z, a.w + b.w + c.w + d.w);
            uint2 u;
            u.x = *(uint32_t*)&p0;
            u.y = *(uint32_t*)&p1;
            ((uint2*)(H + (size_t)row * CDIM))[col] = u;
        }
    }
}

// ---------------------------------------------------------------------------
// Mega kernel: whole post-convert DAG in one launch (grid 6656, 128 threads).
// Roles by blockIdx.x:
//  [0,512)     Kproj   [512,1024) Qproj   [1024,1536) Vproj
//  [1536,3584) S       [3584,3840) softmax
//  [3840,5888) PV (split-K x4, fp32 partials)
//  [5888,6144) H reduce
//  [6144,6656) O
// ---------------------------------------------------------------------------
struct MegaArgs {
    const float *x, *bq, *bk, *bv, *bo;
    float* out;
};
#define MEGA_GRID 6656

__global__ __launch_bounds__(NTHR, 4) void mega(const MegaArgs a) {
    extern __shared__ char smem[];
    const uint32_t sb = smem_u32(smem);
    const int b = blockIdx.x;

    if (b < 512) {                       // K projection (64-row blocks)
        const int kb = b >> 3, nb = b & 7;
        gemm_body<0, 0>(g_xh, g_Wk, a.bk, nullptr, g_K, nullptr,
                        CDIM, CDIM, CDIM, CDIM, kb * 64, nb * 128, sb);
        signal(C_KDONE + kb);
    } else if (b < 1024) {               // Q projection
        const int i = b - 512, qb = i >> 3, nb = i & 7;
        gemm_body<0, 0>(g_xh, g_Wq, a.bq, nullptr, g_Q, nullptr,
                        CDIM, CDIM, CDIM, CDIM, qb * 64, nb * 128, sb);
        signal(C_QDONE + qb);
    } else if (b < 1536) {               // V projection
        const int i = b - 1024, vb = i >> 3, nb = i & 7;
        gemm_body<0, 0>(g_xh, g_Wv, a.bv, nullptr, g_V, nullptr,
                        CDIM, CDIM, CDIM, CDIM, vb * 64, nb * 128, sb);
        signal(C_VKS + (vb >> 4));
    } else if (b < 3584) {               // S = Q @ K^T (fp32)
        const int i = b - 1536, mb = i >> 5, nb = i & 31;
        spin_ge(C_QDONE + mb, 8);
        spin_ge(C_KDONE + 2 * nb, 8);
        spin_ge(C_KDONE + 2 * nb + 1, 8);
        gemm_body<0, 1>(g_Q, g_K, nullptr, nullptr, nullptr, g_S,
                        CDIM, CDIM, CDIM, NTOK, mb * 64, nb * 128, sb);
        signal(C_SCNT + mb);
    } else if (b < 3840) {               // softmax (16-row chunks)
        const int i = b - 3584, mb = i >> 2, rq = i & 3;
        spin_ge(C_SCNT + mb, 32);
        softmax_body(g_S, g_P, mb * 64 + rq * 16, smem);
        signal(C_PDONE + mb);
    } else if (b < 5888) {               // PV split-K partial
        const int i = b - 3840, mb = i >> 5, r = i & 31;
        const int nb = r >> 2, ks = r & 3;
        spin_ge(C_PDONE + mb, 4);
        spin_ge(C_VKS + ks, 128);
        gemm_body<1, 1>(g_P + ks * 1024, g_V + (size_t)ks * 1024 * CDIM,
                        nullptr, nullptr, nullptr, g_Hp + (size_t)ks * NTOK * CDIM,
                        1024, NTOK, 0, CDIM, mb * 64, nb * 128, sb);
        signal(C_HRDY + mb);
    } else if (b < 6144) {               // H reduce
        const int i = b - 5888, mb = i >> 2, rq = i & 3;
        spin_ge(C_HRDY + mb, 32);
        reduce_body(g_Hp, g_H, mb * 64 + rq * 16);
        signal(C_RDONE + mb);
    } else {                             // O = x + H @ Wo^T + bo
        const int i = b - 6144, mb = i >> 3, nb = i & 7;
        spin_ge(C_RDONE + mb, 4);
        gemm_body<0, 2>(g_H, g_Wo, a.bo, a.x, nullptr, a.out,
                        CDIM, CDIM, CDIM, CDIM, mb * 64, nb * 128, sb);
    }
}

// ---------------------------------------------------------------------------
// Fused fp32 -> fp16 convert for x + 4 weights, and counter reset (one launch)
// ---------------------------------------------------------------------------
#define XN4 (NTOK * CDIM / 4)      // 1048576 float4
#define WN4 (CDIM * CDIM / 4)      // 262144 float4

__global__ __launch_bounds__(256) void tohalf_all(
    const float4* __restrict__ x,  __half* __restrict__ xh,
    const float4* __restrict__ w0, __half* __restrict__ o0,
    const float4* __restrict__ w1, __half* __restrict__ o1,
    const float4* __restrict__ w2, __half* __restrict__ o2,
    const float4* __restrict__ w3, __half* __restrict__ o3) {
    if (blockIdx.x < 2) g_cnt[blockIdx.x * 256 + threadIdx.x] = 0;  // reset DAG counters
    int i = blockIdx.x * 256 + threadIdx.x;
    const float4* in;
    __half* out;
    int k;
    if (i < XN4) { in = x; out = xh; k = i; }
    else {
        int j = i - XN4;
        int w = j >> 18;           // / WN4
        k = j & (WN4 - 1);
        switch (w) {
            case 0: in = w0; out = o0; break;
            case 1: in = w1; out = o1; break;
            case 2: in = w2; out = o2; break;
            default: in = w3; out = o3; break;
        }
    }
    float4 v = in[k];
    *(__half2*)(out + (size_t)k * 4)     = __floats2half2_rn(v.x, v.y);
    *(__half2*)(out + (size_t)k * 4 + 2) = __floats2half2_rn(v.z, v.w);
}

// ---------------------------------------------------------------------------
// Launch
// ---------------------------------------------------------------------------
static void* sym(const void* s) { void* p; cudaGetSymbolAddress(&p, s); return p; }

extern "C" void kernel_launch(void* const* d_in, const int* in_sizes, int n_in,
                              void* d_out, int out_size) {
    const float* x  = (const float*)d_in[0];
    const float* Wq = (const float*)d_in[1];
    const float* bq = (const float*)d_in[2];
    const float* Wk = (const float*)d_in[3];
    const float* bk = (const float*)d_in[4];
    const float* Wv = (const float*)d_in[5];
    const float* bv = (const float*)d_in[6];
    const float* Wo = (const float*)d_in[7];
    const float* bo = (const float*)d_in[8];
    float* out = (float*)d_out;

    __half* xh  = (__half*)sym(g_xh);
    __half* Wqh = (__half*)sym(g_Wq);
    __half* Wkh = (__half*)sym(g_Wk);
    __half* Wvh = (__half*)sym(g_Wv);
    __half* Woh = (__half*)sym(g_Wo);

    cudaFuncSetAttribute(mega, cudaFuncAttributeMaxDynamicSharedMemorySize, SMEM_TOTAL);

    // convert + counter reset
    tohalf_all<<<(XN4 + 4 * WN4) / 256, 256>>>(
        (const float4*)x, xh, (const float4*)Wq, Wqh, (const float4*)Wk, Wkh,
        (const float4*)Wv, Wvh, (const float4*)Wo, Woh);

    // everything else: one DAG-scheduled launch
    MegaArgs ma;
    ma.x = x; ma.bq = bq; ma.bk = bk; ma.bv = bv; ma.bo = bo; ma.out = out;
    mega<<<MEGA_GRID, NTHR, SMEM_TOTAL>>>(ma);
}

// round 15
// speedup vs baseline: 1.0051x; 1.0051x over previous
#include <cuda_runtime.h>
#include <cuda_fp16.h>
#include <math_constants.h>
#include <cstdint>

#define NTOK 4096
#define CDIM 1024
#define BM 128
#define BN 128
#define BK 32
#define LDS_A 40    // K-major tile row stride (fp16): 80B, conflict-free ldmatrix
#define LDS_B 136   // trans-B tile row stride (fp16): 272B, conflict-free ldmatrix.trans
#define NTHR 128    // 4 warps, 2x2 of 64x64

// ---------------------------------------------------------------------------
// Scratch (__device__ globals; allocation-free rule)
// ---------------------------------------------------------------------------
__device__ __half g_xh[(size_t)NTOK * CDIM];
__device__ __half g_WqT[(size_t)CDIM * CDIM];   // Wq^T (fp16, [i][o])
__device__ __half g_WkT[(size_t)CDIM * CDIM];
__device__ __half g_WvT[(size_t)CDIM * CDIM];
__device__ __half g_Woh[(size_t)CDIM * CDIM];   // Wo (fp16, row-major [i][o])
__device__ __half g_T[(size_t)CDIM * CDIM];     // T = M^T = Wk^T Wq  ([i][j])
__device__ __half g_W2[(size_t)CDIM * CDIM];    // W2 = Wo Wv          ([i][j])
__device__ __half g_G[(size_t)NTOK * CDIM];     // G = x M
__device__ float  g_S[(size_t)NTOK * NTOK];
__device__ __half g_P[(size_t)NTOK * NTOK];
__device__ float  g_Hp[4ULL * NTOK * CDIM];     // Y split-K partials (fp32)
__device__ __half g_H[(size_t)NTOK * CDIM];     // Y = P x (fp16)
__device__ float  g_u[CDIM];                    // Wk^T bq
__device__ float  g_c[NTOK];                    // x . u  (per-column softmax shift)
__device__ float  g_bo2[CDIM];                  // bo + Wo bv

// dependency counters (reset by the convert kernel each call)
__device__ int g_cnt[256];
#define C_U     0     // target 8
#define C_OBV   1     // target 8
#define C_C     2     // target 32
#define C_TB    8     // 8 ctrs, target 8   (per T i-block)
#define C_W2B   16    // 8 ctrs, target 8   (per W2 i-block)
#define C_GDONE 32    // 32 ctrs, target 8  (per G m-block)
#define C_SCNT  64    // 32 ctrs, target 32 (per S m-block)
#define C_PDONE 96    // 32 ctrs, target 8  (per m-block softmax chunks)
#define C_HRDY  128   // 32 ctrs, target 32 (per m-block Y tiles: 8 nb x 4 ks)
#define C_RDONE 160   // 32 ctrs, target 8  (per m-block reduce chunks)

// ---------------------------------------------------------------------------
// PTX helpers (sm_80-compatible only: cp.async / ldmatrix / mma.sync)
// ---------------------------------------------------------------------------
__device__ __forceinline__ uint32_t smem_u32(const void* p) {
    uint32_t a;
    asm("{ .reg .u64 t; cvta.to.shared.u64 t, %1; cvt.u32.u64 %0, t; }" : "=r"(a) : "l"(p));
    return a;
}

__device__ __forceinline__ void cpa16(uint32_t dst, const __half* src) {
    asm volatile("cp.async.cg.shared.global [%0], [%1], 16;" :: "r"(dst), "l"(src));
}
#define CP_COMMIT() asm volatile("cp.async.commit_group;")
#define CP_WAIT(n)  asm volatile("cp.async.wait_group %0;" :: "n"(n))

#define LDMX4(r, addr) \
    asm volatile("ldmatrix.sync.aligned.m8n8.x4.shared.b16 {%0,%1,%2,%3}, [%4];" \
                 : "=r"((r)[0]), "=r"((r)[1]), "=r"((r)[2]), "=r"((r)[3]) : "r"(addr))

#define LDMX4T(r, addr) \
    asm volatile("ldmatrix.sync.aligned.m8n8.x4.trans.shared.b16 {%0,%1,%2,%3}, [%4];" \
                 : "=r"((r)[0]), "=r"((r)[1]), "=r"((r)[2]), "=r"((r)[3]) : "r"(addr))

__device__ __forceinline__ void mma16816(float* c, const uint32_t* a, const uint32_t* b) {
    asm volatile(
        "mma.sync.aligned.m16n8k16.row.col.f32.f16.f16.f32 "
        "{%0,%1,%2,%3}, {%4,%5,%6,%7}, {%8,%9}, {%0,%1,%2,%3};"
        : "+f"(c[0]), "+f"(c[1]), "+f"(c[2]), "+f"(c[3])
        : "r"(a[0]), "r"(a[1]), "r"(a[2]), "r"(a[3]), "r"(b[0]), "r"(b[1]));
}

// ---------------------------------------------------------------------------
// sync helpers for the in-kernel DAG
// ---------------------------------------------------------------------------
__device__ __forceinline__ void spin_ge(int idx, int target) {
    volatile int* p = (volatile int*)&g_cnt[idx];
    if (threadIdx.x == 0) {
        while (*p < target) __nanosleep(128);
    }
    __syncthreads();
}
__device__ __forceinline__ void signal(int idx) {
    __threadfence();
    __syncthreads();
    if (threadIdx.x == 0) atomicAdd(&g_cnt[idx], 1);
}

// ---------------------------------------------------------------------------
// smem layout: two 128x32 K-major slots (A, B) per stage
// ---------------------------------------------------------------------------
#define TILE_B_BYTES (BM * LDS_A * 2)        // 10240 bytes per slot
#define STAGE_B (2 * TILE_B_BYTES)           // 20480
#define NSTAGE 3
#define SMEM_TOTAL (NSTAGE * STAGE_B)        // 61440  (2 CTAs/SM -> 120KB)

// K-major tile loader: 128 rows x 32 k, 128 threads -> 4 chunks each
__device__ __forceinline__ void load_km(uint32_t sbase, const __half* __restrict__ g,
                                        int row0, int stride, int kcol, int t) {
#pragma unroll
    for (int i = 0; i < 4; ++i) {
        int id = t + i * NTHR;
        int row = id >> 2, q = id & 3;
        cpa16(sbase + (uint32_t)(row * LDS_A + q * 8) * 2,
              g + (size_t)(row0 + row) * stride + kcol + q * 8);
    }
}

// trans-B tile loader: 32 rows (k) x 128 halves (n), n contiguous (stride CDIM)
__device__ __forceinline__ void load_bt(uint32_t sbase, const __half* __restrict__ g,
                                        int n0, int kc, int t) {
#pragma unroll
    for (int i = 0; i < 4; ++i) {
        int id = t + i * NTHR;         // 0..511
        int row = id >> 4;             // 0..31 (k)
        int q = id & 15;               // 16B chunk within 256B row
        cpa16(sbase + (uint32_t)(row * LDS_B + q * 8) * 2,
              g + (size_t)(kc + row) * CDIM + n0 + q * 8);
    }
}

// ---------------------------------------------------------------------------
// GEMM tile body: D[128,128] = A[m0.., :Klen] @ B^T
// BT: 0 = B K-major [n][k], 1 = B row-major [k][n] via ldmatrix.trans
// EPI: 0 = fp16 out (no bias), 1 = fp32 out, 2 = fp32 out + bias + resid
// 4 warps in 2x2, warp tile 64x64
// ---------------------------------------------------------------------------
template <int BT, int EPI>
__device__ __forceinline__ void gemm_body(
    const __half* __restrict__ Ah, const __half* __restrict__ Bg,
    const float* __restrict__ bias, const float* __restrict__ resid,
    __half* __restrict__ oh, float* __restrict__ of,
    int Klen, int Astride, int Bstride, int Nout, int m0, int n0, uint32_t sb)
{
    const int t = threadIdx.x;
    const int lane = t & 31;
    const int wid = t >> 5;            // 0..3
    const int nch = Klen / BK;

    const int warp_m = (wid & 1) * 64;
    const int warp_n = (wid >> 1) * 64;

    const uint32_t aoff = (uint32_t)((warp_m + (lane & 15)) * LDS_A + (lane >> 4) * 8) * 2;
    const uint32_t boff = (uint32_t)((warp_n + ((lane >> 4) & 1) * 8 + (lane & 7)) * LDS_A
                                     + ((lane >> 3) & 1) * 8) * 2;
    const uint32_t boffT = (uint32_t)(((((lane >> 3) & 1) * 8 + (lane & 7)) * LDS_B)
                                      + warp_n + (lane >> 4) * 8) * 2;

    float acc[4][8][4];
#pragma unroll
    for (int i = 0; i < 4; ++i)
#pragma unroll
        for (int j = 0; j < 8; ++j)
#pragma unroll
            for (int r = 0; r < 4; ++r) acc[i][j][r] = 0.0f;

#pragma unroll
    for (int s = 0; s < 2; ++s) {
        uint32_t sg = sb + s * STAGE_B;
        int kc = s * BK;
        load_km(sg, Ah, m0, Astride, kc, t);
        if (BT) load_bt(sg + TILE_B_BYTES, Bg, n0, kc, t);
        else    load_km(sg + TILE_B_BYTES, Bg, n0, Bstride, kc, t);
        CP_COMMIT();
    }

    int slot = 0, slot2 = 2;
    for (int c = 0; c < nch; ++c) {
        if (c + 1 < nch) { CP_WAIT(1); } else { CP_WAIT(0); }
        __syncthreads();

        if (c + 2 < nch) {
            uint32_t sg = sb + slot2 * STAGE_B;
            int kc = (c + 2) * BK;
            load_km(sg, Ah, m0, Astride, kc, t);
            if (BT) load_bt(sg + TILE_B_BYTES, Bg, n0, kc, t);
            else    load_km(sg + TILE_B_BYTES, Bg, n0, Bstride, kc, t);
            CP_COMMIT();
        }

        const uint32_t s0 = sb + slot * STAGE_B;
#pragma unroll
        for (int s = 0; s < 2; ++s) {
            uint32_t ah[4][4], bh[8][2];
#pragma unroll
            for (int i = 0; i < 4; ++i) {
                const uint32_t ao = (uint32_t)(i * 16 * LDS_A + s * 16) * 2;
                LDMX4(ah[i], s0 + aoff + ao);
            }
#pragma unroll
            for (int g = 0; g < 4; ++g) {
                uint32_t r[4];
                if (BT) {
                    const uint32_t bo = (uint32_t)(s * 16 * LDS_B + g * 16) * 2;
                    LDMX4T(r, s0 + TILE_B_BYTES + boffT + bo);
                } else {
                    const uint32_t bo = (uint32_t)(g * 16 * LDS_A + s * 16) * 2;
                    LDMX4(r, s0 + TILE_B_BYTES + boff + bo);
                }
                bh[2 * g][0] = r[0]; bh[2 * g][1] = r[1];
                bh[2 * g + 1][0] = r[2]; bh[2 * g + 1][1] = r[3];
            }
#pragma unroll
            for (int i = 0; i < 4; ++i)
#pragma unroll
                for (int j = 0; j < 8; ++j)
                    mma16816(acc[i][j], ah[i], bh[j]);
        }
        slot = (slot + 1 == NSTAGE) ? 0 : slot + 1;
        slot2 = (slot2 + 1 == NSTAGE) ? 0 : slot2 + 1;
    }

    // epilogue
#pragma unroll
    for (int i = 0; i < 4; ++i) {
        const int r0 = m0 + warp_m + i * 16 + (lane >> 2);
        const int r1 = r0 + 8;
#pragma unroll
        for (int j = 0; j < 8; ++j) {
            const int cc = n0 + warp_n + j * 8 + (lane & 3) * 2;
            float v0 = acc[i][j][0], v1 = acc[i][j][1];
            float v2 = acc[i][j][2], v3 = acc[i][j][3];

            if (EPI == 1) {
                *(float2*)(of + (size_t)r0 * Nout + cc) = make_float2(v0, v1);
                *(float2*)(of + (size_t)r1 * Nout + cc) = make_float2(v2, v3);
            } else if (EPI == 2) {
                const float b0 = bias[cc], b1 = bias[cc + 1];
                float2 ra = *(const float2*)(resid + (size_t)r0 * Nout + cc);
                float2 rb = *(const float2*)(resid + (size_t)r1 * Nout + cc);
                *(float2*)(of + (size_t)r0 * Nout + cc) = make_float2(v0 + b0 + ra.x, v1 + b1 + ra.y);
                *(float2*)(of + (size_t)r1 * Nout + cc) = make_float2(v2 + b0 + rb.x, v3 + b1 + rb.y);
            } else {
                *(__half2*)(oh + (size_t)r0 * Nout + cc) =
                    __halves2half2(__float2half_rn(v0), __float2half_rn(v1));
                *(__half2*)(oh + (size_t)r1 * Nout + cc) =
                    __halves2half2(__float2half_rn(v2), __float2half_rn(v3));
            }
        }
    }
}

// ---------------------------------------------------------------------------
// softmax body: 16 rows, 128 threads, fp32 S (+ per-column shift c) -> fp16 P
// ---------------------------------------------------------------------------
__device__ __forceinline__ float warpMax(float v) {
#pragma unroll
    for (int o = 16; o > 0; o >>= 1) v = fmaxf(v, __shfl_xor_sync(0xffffffffu, v, o));
    return v;
}
__device__ __forceinline__ float warpSum(float v) {
#pragma unroll
    for (int o = 16; o > 0; o >>= 1) v += __shfl_xor_sync(0xffffffffu, v, o);
    return v;
}

__device__ void softmax_body(const float* __restrict__ S, __half* __restrict__ P,
                             int row0, char* smemraw) {
    float* red = (float*)smemraw;
    const int t = threadIdx.x;
    const int lane = t & 31, wid = t >> 5;

    // per-column shift (same for all rows this CTA handles)
    float4 cs[8];
#pragma unroll
    for (int i = 0; i < 8; ++i) cs[i] = ((const float4*)g_c)[t + NTHR * i];

    for (int r = 0; r < 16; ++r) {
        const int row = row0 + r;
        const float4* pr = (const float4*)(S + (size_t)row * NTOK);
        float4 v[8];
#pragma unroll
        for (int i = 0; i < 8; ++i) {
            v[i] = pr[t + NTHR * i];
            v[i].x += cs[i].x; v[i].y += cs[i].y;
            v[i].z += cs[i].z; v[i].w += cs[i].w;
        }

        float m = -CUDART_INF_F;
#pragma unroll
        for (int i = 0; i < 8; ++i)
            m = fmaxf(m, fmaxf(fmaxf(v[i].x, v[i].y), fmaxf(v[i].z, v[i].w)));
        m = warpMax(m);
        if (lane == 0) red[wid] = m;
        __syncthreads();
        if (t < 32) {
            float z = (t < 4) ? red[t] : -CUDART_INF_F;
            z = warpMax(z);
            if (t == 0) red[4] = z;
        }
        __syncthreads();
        m = red[4];

        float s = 0.0f;
#pragma unroll
        for (int i = 0; i < 8; ++i) {
            v[i].x = __expf(v[i].x - m); v[i].y = __expf(v[i].y - m);
            v[i].z = __expf(v[i].z - m); v[i].w = __expf(v[i].w - m);
            s += (v[i].x + v[i].y) + (v[i].z + v[i].w);
        }
        s = warpSum(s);
        __syncthreads();
        if (lane == 0) red[wid] = s;
        __syncthreads();
        if (t < 32) {
            float z = (t < 4) ? red[t] : 0.0f;
            z = warpSum(z);
            if (t == 0) red[4] = z;
        }
        __syncthreads();
        const float inv = 1.0f / red[4];

        uint2* po = (uint2*)(P + (size_t)row * NTOK);
#pragma unroll
        for (int i = 0; i < 8; ++i) {
            __half2 h0 = __floats2half2_rn(v[i].x * inv, v[i].y * inv);
            __half2 h1 = __floats2half2_rn(v[i].z * inv, v[i].w * inv);
            uint2 u;
            u.x = *(uint32_t*)&h0;
            u.y = *(uint32_t*)&h1;
            po[t + NTHR * i] = u;
        }
        __syncthreads();
    }
}

// ---------------------------------------------------------------------------
// H reduce body: H = sum of 4 fp32 partials -> fp16.  16 rows, 128 threads.
// ---------------------------------------------------------------------------
__device__ void reduce_body(const float* __restrict__ Hp, __half* __restrict__ H, int row0) {
    const int t = threadIdx.x;
    const size_t plane = (size_t)NTOK * CDIM;
    for (int r = 0; r < 16; ++r) {
        const int row = row0 + r;
#pragma unroll
        for (int i = 0; i < 2; ++i) {
            const int col = t + i * NTHR;
            const float4* h0 = (const float4*)(Hp + (size_t)row * CDIM);
            const float4* h1 = (const float4*)(Hp + plane + (size_t)row * CDIM);
            const float4* h2 = (const float4*)(Hp + 2 * plane + (size_t)row * CDIM);
            const float4* h3 = (const float4*)(Hp + 3 * plane + (size_t)row * CDIM);
            float4 a = h0[col], b = h1[col], c = h2[col], d = h3[col];
            __half2 p0 = __floats2half2_rn(a.x + b.x + c.x + d.x, a.y + b.y + c.y + d.y);
            __half2 p1 = __floats2half2_rn(a.z + b.z + c.z + d.z, a.w + b.w + c.w + d.w);
            uint2 u;
            u.x = *(uint32_t*)&p0;
            u.y = *(uint32_t*)&p1;
            ((uint2*)(H + (size_t)row * CDIM))[col] = u;
        }
    }
}

// ---------------------------------------------------------------------------
// small-GEMV bodies (aux)
// ---------------------------------------------------------------------------
// out[i] = base(i) + dot(Wrow_fp16[i][:], vec_fp32)
__device__ void gemv_body(const __half* __restrict__ W, const float* __restrict__ vec,
                          const float* __restrict__ base, float* __restrict__ out, int i0) {
    const int i = i0 + threadIdx.x;
    const __half2* w = (const __half2*)(W + (size_t)i * CDIM);
    float acc = 0.0f;
    for (int o = 0; o < CDIM / 2; ++o) {
        float2 wv = __half22float2(w[o]);
        acc += wv.x * vec[2 * o] + wv.y * vec[2 * o + 1];
    }
    out[i] = (base ? base[i] : 0.0f) + acc;
}

// ---------------------------------------------------------------------------
// Mega kernel. Roles by blockIdx.x (grid 3184):
//  [0,8)       u = Wk^T bq           [8,16)  bo2 = bo + Wo bv
//  [16,80)     T = Wk^T Wq           [80,144) W2 = Wo Wv
//  [144,400)   G = x M (waits T blocks)
//  [400,432)   c = x . u  (waits u)
//  [432,1456)  S = G x^T
//  [1456,1712) softmax(+c)
//  [1712,2736) Y = P x (split-K x4)
//  [2736,2992) reduce
//  [2992,3248) O = x + Y W2^T + bo2
// ---------------------------------------------------------------------------
struct MegaArgs {
    const float *x, *bq, *bv, *bo;
    float* out;
};
#define MEGA_GRID 3248

__global__ __launch_bounds__(NTHR, 2) void mega(const MegaArgs a) {
    extern __shared__ char smem[];
    const uint32_t sb = smem_u32(smem);
    const int b = blockIdx.x;

    if (b < 8) {                         // u = Wk^T bq
        gemv_body(g_WkT, a.bq, nullptr, g_u, b * NTHR);
        signal(C_U);
    } else if (b < 16) {                 // bo2 = bo + Wo bv
        gemv_body(g_Woh, a.bv, a.bo, g_bo2, (b - 8) * NTHR);
        signal(C_OBV);
    } else if (b < 80) {                 // T = Wk^T Wq  (T[i][j] = sum_o WkT[i][o] WqT[j][o])
        const int i = b - 16, tb = i >> 3, nb = i & 7;
        gemm_body<0, 0>(g_WkT, g_WqT, nullptr, nullptr, g_T, nullptr,
                        CDIM, CDIM, CDIM, CDIM, tb * 128, nb * 128, sb);
        signal(C_TB + tb);
    } else if (b < 144) {                // W2 = Wo Wv  (W2[i][j] = sum_o Wo[i][o] WvT[j][o])
        const int i = b - 80, tb = i >> 3, nb = i & 7;
        gemm_body<0, 0>(g_Woh, g_WvT, nullptr, nullptr, g_W2, nullptr,
                        CDIM, CDIM, CDIM, CDIM, tb * 128, nb * 128, sb);
        signal(C_W2B + tb);
    } else if (b < 400) {                // G = x M  (G[m][i] = sum_j xh[m][j] T[i][j])
        const int i = b - 144, gb = i >> 3, nb = i & 7;
        spin_ge(C_TB + nb, 8);
        gemm_body<0, 0>(g_xh, g_T, nullptr, nullptr, g_G, nullptr,
                        CDIM, CDIM, CDIM, CDIM, gb * 128, nb * 128, sb);
        signal(C_GDONE + gb);
    } else if (b < 432) {                // c[n] = dot(xh[n], u)
        const int i = b - 400;
        spin_ge(C_U, 8);
        gemv_body(g_xh, g_u, nullptr, g_c, i * NTHR);
        signal(C_C);
    } else if (b < 1456) {               // S = G x^T (fp32)
        const int i = b - 432, mb = i >> 5, nb = i & 31;
        spin_ge(C_GDONE + mb, 8);
        gemm_body<0, 1>(g_G, g_xh, nullptr, nullptr, nullptr, g_S,
                        CDIM, CDIM, CDIM, NTOK, mb * 128, nb * 128, sb);
        signal(C_SCNT + mb);
    } else if (b < 1712) {               // softmax(+c)
        const int i = b - 1456, mb = i >> 3, rq = i & 7;
        spin_ge(C_SCNT + mb, 32);
        spin_ge(C_C, 32);
        softmax_body(g_S, g_P, mb * 128 + rq * 16, smem);
        signal(C_PDONE + mb);
    } else if (b < 2736) {               // Y = P x  (split-K x4, fp32 partials)
        const int i = b - 1712, mb = i >> 5, r = i & 31;
        const int nb = r >> 2, ks = r & 3;
        spin_ge(C_PDONE + mb, 8);
        gemm_body<1, 1>(g_P + ks * 1024, g_xh + (size_t)ks * 1024 * CDIM,
                        nullptr, nullptr, nullptr, g_Hp + (size_t)ks * NTOK * CDIM,
                        1024, NTOK, 0, CDIM, mb * 128, nb * 128, sb);
        signal(C_HRDY + mb);
    } else if (b < 2992) {               // reduce
        const int i = b - 2736, mb = i >> 3, rq = i & 7;
        spin_ge(C_HRDY + mb, 32);
        reduce_body(g_Hp, g_H, mb * 128 + rq * 16);
        signal(C_RDONE + mb);
    } else {                             // O = x + Y W2^T + bo2
        const int i = b - 2992, mb = i >> 3, nb = i & 7;
        spin_ge(C_RDONE + mb, 8);
        spin_ge(C_W2B + nb, 8);
        spin_ge(C_OBV, 8);
        gemm_body<0, 2>(g_H, g_W2, g_bo2, a.x, nullptr, a.out,
                        CDIM, CDIM, CDIM, CDIM, mb * 128, nb * 128, sb);
    }
}

// ---------------------------------------------------------------------------
// Transposing fp32->fp16 convert for Wq, Wk, Wv (smem-tiled, coalesced both sides)
// ---------------------------------------------------------------------------
__global__ __launch_bounds__(256) void transpose_half(
    const float* __restrict__ w0, __half* __restrict__ o0,
    const float* __restrict__ w1, __half* __restrict__ o1,
    const float* __restrict__ w2, __half* __restrict__ o2) {
    __shared__ float s[64][65];
    const int b = blockIdx.x;
    const int mat = b >> 8, tile = b & 255;
    const int ti = tile >> 4, tj = tile & 15;       // 64x64 tile (rows=o, cols=i)
    const float* src = (mat == 0) ? w0 : (mat == 1) ? w1 : w2;
    __half* dst = (mat == 0) ? o0 : (mat == 1) ? o1 : o2;
    const int t = threadIdx.x;
    const int r = t >> 2, cq = (t & 3) * 16;

#pragma unroll
    for (int j = 0; j < 16; ++j)
        s[r][cq + j] = src[(size_t)(ti * 64 + r) * CDIM + tj * 64 + cq + j];
    __syncthreads();
#pragma unroll
    for (int j = 0; j < 16; ++j)
        dst[(size_t)(tj * 64 + r) * CDIM + ti * 64 + cq + j] = __float2half_rn(s[cq + j][r]);
}

// ---------------------------------------------------------------------------
// fp32->fp16 convert for x and Wo, and counter reset (one launch)
// ---------------------------------------------------------------------------
#define XN4 (NTOK * CDIM / 4)      // 1048576 float4
#define WN4 (CDIM * CDIM / 4)      // 262144 float4

__global__ __launch_bounds__(256) void tohalf2(
    const float4* __restrict__ x,  __half* __restrict__ xh,
    const float4* __restrict__ wo, __half* __restrict__ woh) {
    if (blockIdx.x == 0) g_cnt[threadIdx.x] = 0;   // reset DAG counters
    int i = blockIdx.x * 256 + threadIdx.x;
    const float4* in;
    __half* out;
    int k;
    if (i < XN4) { in = x; out = xh; k = i; }
    else         { in = wo; out = woh; k = i - XN4; }
    float4 v = in[k];
    *(__half2*)(out + (size_t)k * 4)     = __floats2half2_rn(v.x, v.y);
    *(__half2*)(out + (size_t)k * 4 + 2) = __floats2half2_rn(v.z, v.w);
}

// ---------------------------------------------------------------------------
// Launch
// ---------------------------------------------------------------------------
static void* sym(const void* s) { void* p; cudaGetSymbolAddress(&p, s); return p; }

extern "C" void kernel_launch(void* const* d_in, const int* in_sizes, int n_in,
                              void* d_out, int out_size) {
    const float* x  = (const float*)d_in[0];
    const float* Wq = (const float*)d_in[1];
    const float* bq = (const float*)d_in[2];
    const float* Wk = (const float*)d_in[3];
    const float* Wv = (const float*)d_in[5];
    const float* bv = (const float*)d_in[6];
    const float* Wo = (const float*)d_in[7];
    const float* bo = (const float*)d_in[8];
    float* out = (float*)d_out;

    __half* xh   = (__half*)sym(g_xh);
    __half* WqT  = (__half*)sym(g_WqT);
    __half* WkT  = (__half*)sym(g_WkT);
    __half* WvT  = (__half*)sym(g_WvT);
    __half* Woh  = (__half*)sym(g_Woh);

    cudaFuncSetAttribute(mega, cudaFuncAttributeMaxDynamicSharedMemorySize, SMEM_TOTAL);

    // prep: transposed weights, x/Wo converts, counter reset
    transpose_half<<<768, 256>>>(Wq, WqT, Wk, WkT, Wv, WvT);
    tohalf2<<<(XN4 + WN4) / 256, 256>>>((const float4*)x, xh, (const float4*)Wo, Woh);

    // everything else: one DAG-scheduled launch
    MegaArgs ma;
    ma.x = x; ma.bq = bq; ma.bv = bv; ma.bo = bo; ma.out = out;
    mega<<<MEGA_GRID, NTHR, SMEM_TOTAL>>>(ma);
}

// round 16
// speedup vs baseline: 1.0665x; 1.0611x over previous
#include <cuda_runtime.h>
#include <cuda_fp16.h>
#include <math_constants.h>
#include <cstdint>

#define NTOK 4096
#define CDIM 1024
#define BM 128
#define BN 128
#define BK 32
#define LDS_A 40    // K-major tile row stride (fp16): 80B, conflict-free ldmatrix
#define LDS_B 136   // trans-B tile row stride (fp16): 272B, conflict-free ldmatrix.trans
#define NTHR 128    // 4 warps, 2x2 of 64x64

// ---------------------------------------------------------------------------
// Scratch (__device__ globals; allocation-free rule)
// ---------------------------------------------------------------------------
__device__ __half g_xh[(size_t)NTOK * CDIM];
__device__ __half g_Wqh[(size_t)CDIM * CDIM];   // Wq fp16 as stored [n][i]
__device__ __half g_WkT[(size_t)CDIM * CDIM];   // Wk^T fp16 [i][n]
__device__ __half g_Wvh[(size_t)CDIM * CDIM];   // Wv fp16 as stored [j][i]
__device__ __half g_Woh[(size_t)CDIM * CDIM];   // Wo fp16 as stored [n][j]
__device__ __half g_T[(size_t)CDIM * CDIM];     // T[i][j] = sum_n Wk[n][i] Wq[n][j]
__device__ __half g_W2[(size_t)CDIM * CDIM];    // W2[n][i] = sum_j Wo[n][j] Wv[j][i]
__device__ __half g_G[(size_t)NTOK * CDIM];     // G = x M  (M = T^T)
__device__ float  g_S[(size_t)NTOK * NTOK];
__device__ __half g_P[(size_t)NTOK * NTOK];
__device__ float  g_Hp[4ULL * NTOK * CDIM];     // Y split-K partials (fp32)
__device__ __half g_H[(size_t)NTOK * CDIM];     // Y = P x (fp16)
__device__ float  g_u[CDIM];                    // Wk^T bq
__device__ float  g_c[NTOK];                    // x . u  (per-column softmax shift)
__device__ float  g_bo2[CDIM];                  // bo + Wo bv

// dependency counters (reset by prep each call)
__device__ int g_cnt[256];
#define C_U     0     // target 8
#define C_OBV   1     // target 8
#define C_C     2     // target 32
#define C_TB    8     // 8 ctrs, target 8   (per T i-block)
#define C_W2B   16    // 8 ctrs, target 8   (per W2 n-block)
#define C_GDONE 32    // 32 ctrs, target 8  (per G m-block)
#define C_SCNT  64    // 32 ctrs, target 32 (per S m-block)
#define C_PDONE 96    // 32 ctrs, target 8  (per m-block softmax chunks)
#define C_HRDY  128   // 32 ctrs, target 32 (per m-block Y tiles: 8 nb x 4 ks)
#define C_RDONE 160   // 32 ctrs, target 8  (per m-block reduce chunks)

// ---------------------------------------------------------------------------
// PTX helpers (sm_80-compatible only: cp.async / ldmatrix / mma.sync)
// ---------------------------------------------------------------------------
__device__ __forceinline__ uint32_t smem_u32(const void* p) {
    uint32_t a;
    asm("{ .reg .u64 t; cvta.to.shared.u64 t, %1; cvt.u32.u64 %0, t; }" : "=r"(a) : "l"(p));
    return a;
}

__device__ __forceinline__ void cpa16(uint32_t dst, const __half* src) {
    asm volatile("cp.async.cg.shared.global [%0], [%1], 16;" :: "r"(dst), "l"(src));
}
#define CP_COMMIT() asm volatile("cp.async.commit_group;")
#define CP_WAIT(n)  asm volatile("cp.async.wait_group %0;" :: "n"(n))

#define LDMX4(r, addr) \
    asm volatile("ldmatrix.sync.aligned.m8n8.x4.shared.b16 {%0,%1,%2,%3}, [%4];" \
                 : "=r"((r)[0]), "=r"((r)[1]), "=r"((r)[2]), "=r"((r)[3]) : "r"(addr))

#define LDMX4T(r, addr) \
    asm volatile("ldmatrix.sync.aligned.m8n8.x4.trans.shared.b16 {%0,%1,%2,%3}, [%4];" \
                 : "=r"((r)[0]), "=r"((r)[1]), "=r"((r)[2]), "=r"((r)[3]) : "r"(addr))

__device__ __forceinline__ void mma16816(float* c, const uint32_t* a, const uint32_t* b) {
    asm volatile(
        "mma.sync.aligned.m16n8k16.row.col.f32.f16.f16.f32 "
        "{%0,%1,%2,%3}, {%4,%5,%6,%7}, {%8,%9}, {%0,%1,%2,%3};"
        : "+f"(c[0]), "+f"(c[1]), "+f"(c[2]), "+f"(c[3])
        : "r"(a[0]), "r"(a[1]), "r"(a[2]), "r"(a[3]), "r"(b[0]), "r"(b[1]));
}

// ---------------------------------------------------------------------------
// sync helpers for the in-kernel DAG
// ---------------------------------------------------------------------------
__device__ __forceinline__ void spin_ge(int idx, int target) {
    volatile int* p = (volatile int*)&g_cnt[idx];
    if (threadIdx.x == 0) {
        while (*p < target) __nanosleep(128);
    }
    __syncthreads();
}
__device__ __forceinline__ void signal(int idx) {
    __threadfence();
    __syncthreads();
    if (threadIdx.x == 0) atomicAdd(&g_cnt[idx], 1);
}

// ---------------------------------------------------------------------------
// smem layout: two 128x32 K-major slots (A, B) per stage
// ---------------------------------------------------------------------------
#define TILE_B_BYTES (BM * LDS_A * 2)        // 10240 bytes per slot
#define STAGE_B (2 * TILE_B_BYTES)           // 20480
#define NSTAGE 3
#define SMEM_TOTAL (NSTAGE * STAGE_B)        // 61440  (2 CTAs/SM -> 120KB)

// K-major tile loader: 128 rows x 32 k, 128 threads -> 4 chunks each
__device__ __forceinline__ void load_km(uint32_t sbase, const __half* __restrict__ g,
                                        int row0, int stride, int kcol, int t) {
#pragma unroll
    for (int i = 0; i < 4; ++i) {
        int id = t + i * NTHR;
        int row = id >> 2, q = id & 3;
        cpa16(sbase + (uint32_t)(row * LDS_A + q * 8) * 2,
              g + (size_t)(row0 + row) * stride + kcol + q * 8);
    }
}

// trans-B tile loader: 32 rows (k) x 128 halves (n), n contiguous (stride CDIM)
__device__ __forceinline__ void load_bt(uint32_t sbase, const __half* __restrict__ g,
                                        int n0, int kc, int t) {
#pragma unroll
    for (int i = 0; i < 4; ++i) {
        int id = t + i * NTHR;         // 0..511
        int row = id >> 4;             // 0..31 (k)
        int q = id & 15;               // 16B chunk within 256B row
        cpa16(sbase + (uint32_t)(row * LDS_B + q * 8) * 2,
              g + (size_t)(kc + row) * CDIM + n0 + q * 8);
    }
}

// ---------------------------------------------------------------------------
// GEMM tile body: D[128,128] = A[m0.., :Klen] @ B^T
// BT: 0 = B K-major [n][k], 1 = B row-major [k][n] via ldmatrix.trans
// EPI: 0 = fp16 out (no bias), 1 = fp32 out, 2 = fp32 out + bias + resid
// 4 warps in 2x2, warp tile 64x64
// ---------------------------------------------------------------------------
template <int BT, int EPI>
__device__ __forceinline__ void gemm_body(
    const __half* __restrict__ Ah, const __half* __restrict__ Bg,
    const float* __restrict__ bias, const float* __restrict__ resid,
    __half* __restrict__ oh, float* __restrict__ of,
    int Klen, int Astride, int Bstride, int Nout, int m0, int n0, uint32_t sb)
{
    const int t = threadIdx.x;
    const int lane = t & 31;
    const int wid = t >> 5;            // 0..3
    const int nch = Klen / BK;

    const int warp_m = (wid & 1) * 64;
    const int warp_n = (wid >> 1) * 64;

    const uint32_t aoff = (uint32_t)((warp_m + (lane & 15)) * LDS_A + (lane >> 4) * 8) * 2;
    const uint32_t boff = (uint32_t)((warp_n + ((lane >> 4) & 1) * 8 + (lane & 7)) * LDS_A
                                     + ((lane >> 3) & 1) * 8) * 2;
    const uint32_t boffT = (uint32_t)(((((lane >> 3) & 1) * 8 + (lane & 7)) * LDS_B)
                                      + warp_n + (lane >> 4) * 8) * 2;

    float acc[4][8][4];
#pragma unroll
    for (int i = 0; i < 4; ++i)
#pragma unroll
        for (int j = 0; j < 8; ++j)
#pragma unroll
            for (int r = 0; r < 4; ++r) acc[i][j][r] = 0.0f;

#pragma unroll
    for (int s = 0; s < 2; ++s) {
        uint32_t sg = sb + s * STAGE_B;
        int kc = s * BK;
        load_km(sg, Ah, m0, Astride, kc, t);
        if (BT) load_bt(sg + TILE_B_BYTES, Bg, n0, kc, t);
        else    load_km(sg + TILE_B_BYTES, Bg, n0, Bstride, kc, t);
        CP_COMMIT();
    }

    int slot = 0, slot2 = 2;
    for (int c = 0; c < nch; ++c) {
        if (c + 1 < nch) { CP_WAIT(1); } else { CP_WAIT(0); }
        __syncthreads();

        if (c + 2 < nch) {
            uint32_t sg = sb + slot2 * STAGE_B;
            int kc = (c + 2) * BK;
            load_km(sg, Ah, m0, Astride, kc, t);
            if (BT) load_bt(sg + TILE_B_BYTES, Bg, n0, kc, t);
            else    load_km(sg + TILE_B_BYTES, Bg, n0, Bstride, kc, t);
            CP_COMMIT();
        }

        const uint32_t s0 = sb + slot * STAGE_B;
#pragma unroll
        for (int s = 0; s < 2; ++s) {
            uint32_t ah[4][4], bh[8][2];
#pragma unroll
            for (int i = 0; i < 4; ++i) {
                const uint32_t ao = (uint32_t)(i * 16 * LDS_A + s * 16) * 2;
                LDMX4(ah[i], s0 + aoff + ao);
            }
#pragma unroll
            for (int g = 0; g < 4; ++g) {
                uint32_t r[4];
                if (BT) {
                    const uint32_t bo = (uint32_t)(s * 16 * LDS_B + g * 16) * 2;
                    LDMX4T(r, s0 + TILE_B_BYTES + boffT + bo);
                } else {
                    const uint32_t bo = (uint32_t)(g * 16 * LDS_A + s * 16) * 2;
                    LDMX4(r, s0 + TILE_B_BYTES + boff + bo);
                }
                bh[2 * g][0] = r[0]; bh[2 * g][1] = r[1];
                bh[2 * g + 1][0] = r[2]; bh[2 * g + 1][1] = r[3];
            }
#pragma unroll
            for (int i = 0; i < 4; ++i)
#pragma unroll
                for (int j = 0; j < 8; ++j)
                    mma16816(acc[i][j], ah[i], bh[j]);
        }
        slot = (slot + 1 == NSTAGE) ? 0 : slot + 1;
        slot2 = (slot2 + 1 == NSTAGE) ? 0 : slot2 + 1;
    }

    // epilogue
#pragma unroll
    for (int i = 0; i < 4; ++i) {
        const int r0 = m0 + warp_m + i * 16 + (lane >> 2);
        const int r1 = r0 + 8;
#pragma unroll
        for (int j = 0; j < 8; ++j) {
            const int cc = n0 + warp_n + j * 8 + (lane & 3) * 2;
            float v0 = acc[i][j][0], v1 = acc[i][j][1];
            float v2 = acc[i][j][2], v3 = acc[i][j][3];

            if (EPI == 1) {
                *(float2*)(of + (size_t)r0 * Nout + cc) = make_float2(v0, v1);
                *(float2*)(of + (size_t)r1 * Nout + cc) = make_float2(v2, v3);
            } else if (EPI == 2) {
                const float b0 = bias[cc], b1 = bias[cc + 1];
                float2 ra = *(const float2*)(resid + (size_t)r0 * Nout + cc);
                float2 rb = *(const float2*)(resid + (size_t)r1 * Nout + cc);
                *(float2*)(of + (size_t)r0 * Nout + cc) = make_float2(v0 + b0 + ra.x, v1 + b1 + ra.y);
                *(float2*)(of + (size_t)r1 * Nout + cc) = make_float2(v2 + b0 + rb.x, v3 + b1 + rb.y);
            } else {
                *(__half2*)(oh + (size_t)r0 * Nout + cc) =
                    __halves2half2(__float2half_rn(v0), __float2half_rn(v1));
                *(__half2*)(oh + (size_t)r1 * Nout + cc) =
                    __halves2half2(__float2half_rn(v2), __float2half_rn(v3));
            }
        }
    }
}

// ---------------------------------------------------------------------------
// softmax body: 16 rows, 128 threads, fp32 S (+ per-column shift c) -> fp16 P
// ---------------------------------------------------------------------------
__device__ __forceinline__ float warpMax(float v) {
#pragma unroll
    for (int o = 16; o > 0; o >>= 1) v = fmaxf(v, __shfl_xor_sync(0xffffffffu, v, o));
    return v;
}
__device__ __forceinline__ float warpSum(float v) {
#pragma unroll
    for (int o = 16; o > 0; o >>= 1) v += __shfl_xor_sync(0xffffffffu, v, o);
    return v;
}

__device__ void softmax_body(const float* __restrict__ S, __half* __restrict__ P,
                             int row0, char* smemraw) {
    float* red = (float*)smemraw;
    const int t = threadIdx.x;
    const int lane = t & 31, wid = t >> 5;

    float4 cs[8];
#pragma unroll
    for (int i = 0; i < 8; ++i) cs[i] = ((const float4*)g_c)[t + NTHR * i];

    for (int r = 0; r < 16; ++r) {
        const int row = row0 + r;
        const float4* pr = (const float4*)(S + (size_t)row * NTOK);
        float4 v[8];
#pragma unroll
        for (int i = 0; i < 8; ++i) {
            v[i] = pr[t + NTHR * i];
            v[i].x += cs[i].x; v[i].y += cs[i].y;
            v[i].z += cs[i].z; v[i].w += cs[i].w;
        }

        float m = -CUDART_INF_F;
#pragma unroll
        for (int i = 0; i < 8; ++i)
            m = fmaxf(m, fmaxf(fmaxf(v[i].x, v[i].y), fmaxf(v[i].z, v[i].w)));
        m = warpMax(m);
        if (lane == 0) red[wid] = m;
        __syncthreads();
        if (t < 32) {
            float z = (t < 4) ? red[t] : -CUDART_INF_F;
            z = warpMax(z);
            if (t == 0) red[4] = z;
        }
        __syncthreads();
        m = red[4];

        float s = 0.0f;
#pragma unroll
        for (int i = 0; i < 8; ++i) {
            v[i].x = __expf(v[i].x - m); v[i].y = __expf(v[i].y - m);
            v[i].z = __expf(v[i].z - m); v[i].w = __expf(v[i].w - m);
            s += (v[i].x + v[i].y) + (v[i].z + v[i].w);
        }
        s = warpSum(s);
        __syncthreads();
        if (lane == 0) red[wid] = s;
        __syncthreads();
        if (t < 32) {
            float z = (t < 4) ? red[t] : 0.0f;
            z = warpSum(z);
            if (t == 0) red[4] = z;
        }
        __syncthreads();
        const float inv = 1.0f / red[4];

        uint2* po = (uint2*)(P + (size_t)row * NTOK);
#pragma unroll
        for (int i = 0; i < 8; ++i) {
            __half2 h0 = __floats2half2_rn(v[i].x * inv, v[i].y * inv);
            __half2 h1 = __floats2half2_rn(v[i].z * inv, v[i].w * inv);
            uint2 u;
            u.x = *(uint32_t*)&h0;
            u.y = *(uint32_t*)&h1;
            po[t + NTHR * i] = u;
        }
        __syncthreads();
    }
}

// ---------------------------------------------------------------------------
// H reduce body: H = sum of 4 fp32 partials -> fp16.  16 rows, 128 threads.
// ---------------------------------------------------------------------------
__device__ void reduce_body(const float* __restrict__ Hp, __half* __restrict__ H, int row0) {
    const int t = threadIdx.x;
    const size_t plane = (size_t)NTOK * CDIM;
    for (int r = 0; r < 16; ++r) {
        const int row = row0 + r;
#pragma unroll
        for (int i = 0; i < 2; ++i) {
            const int col = t + i * NTHR;
            const float4* h0 = (const float4*)(Hp + (size_t)row * CDIM);
            const float4* h1 = (const float4*)(Hp + plane + (size_t)row * CDIM);
            const float4* h2 = (const float4*)(Hp + 2 * plane + (size_t)row * CDIM);
            const float4* h3 = (const float4*)(Hp + 3 * plane + (size_t)row * CDIM);
            float4 a = h0[col], b = h1[col], c = h2[col], d = h3[col];
            __half2 p0 = __floats2half2_rn(a.x + b.x + c.x + d.x, a.y + b.y + c.y + d.y);
            __half2 p1 = __floats2half2_rn(a.z + b.z + c.z + d.z, a.w + b.w + c.w + d.w);
            uint2 u;
            u.x = *(uint32_t*)&p0;
            u.y = *(uint32_t*)&p1;
            ((uint2*)(H + (size_t)row * CDIM))[col] = u;
        }
    }
}

// ---------------------------------------------------------------------------
// small-GEMV body: out[i] = base(i) + dot(Wrow_fp16[i][:], vec_fp32)
// ---------------------------------------------------------------------------
__device__ void gemv_body(const __half* __restrict__ W, const float* __restrict__ vec,
                          const float* __restrict__ base, float* __restrict__ out, int i0) {
    const int i = i0 + threadIdx.x;
    const __half2* w = (const __half2*)(W + (size_t)i * CDIM);
    float acc = 0.0f;
    for (int o = 0; o < CDIM / 2; ++o) {
        float2 wv = __half22float2(w[o]);
        acc += wv.x * vec[2 * o] + wv.y * vec[2 * o + 1];
    }
    out[i] = (base ? base[i] : 0.0f) + acc;
}

// ---------------------------------------------------------------------------
// Mega kernel. Roles by blockIdx.x (grid 3248):
//  [0,8)       u = Wk^T bq           [8,16)  bo2 = bo + Wo bv
//  [16,80)     T = WkT x Wq (BT)     [80,144) W2 = Wo x Wv (BT)
//  [144,400)   G = x M (waits T blocks)
//  [400,432)   c = x . u  (waits u)
//  [432,1456)  S = G x^T
//  [1456,1712) softmax(+c)
//  [1712,2736) Y = P x (split-K x4)
//  [2736,2992) reduce
//  [2992,3248) O = x + Y W2^T + bo2
// ---------------------------------------------------------------------------
struct MegaArgs {
    const float *x, *bq, *bv, *bo;
    float* out;
};
#define MEGA_GRID 3248

__global__ __launch_bounds__(NTHR, 2) void mega(const MegaArgs a) {
    extern __shared__ char smem[];
    const uint32_t sb = smem_u32(smem);
    const int b = blockIdx.x;

    if (b < 8) {                         // u = Wk^T bq
        gemv_body(g_WkT, a.bq, nullptr, g_u, b * NTHR);
        signal(C_U);
    } else if (b < 16) {                 // bo2 = bo + Wo bv
        gemv_body(g_Woh, a.bv, a.bo, g_bo2, (b - 8) * NTHR);
        signal(C_OBV);
    } else if (b < 80) {                 // T[i][j] = sum_n WkT[i][n] Wq[n][j]  (BT path)
        const int i = b - 16, tb = i >> 3, nb = i & 7;
        gemm_body<1, 0>(g_WkT, g_Wqh, nullptr, nullptr, g_T, nullptr,
                        CDIM, CDIM, 0, CDIM, tb * 128, nb * 128, sb);
        signal(C_TB + tb);
    } else if (b < 144) {                // W2[n][i] = sum_j Wo[n][j] Wv[j][i]  (BT path)
        const int i = b - 80, tb = i >> 3, nb = i & 7;
        gemm_body<1, 0>(g_Woh, g_Wvh, nullptr, nullptr, g_W2, nullptr,
                        CDIM, CDIM, 0, CDIM, tb * 128, nb * 128, sb);
        signal(C_W2B + tb);
    } else if (b < 400) {                // G = x M  (G[m][i] = sum_j xh[m][j] T[i][j])
        const int i = b - 144, gb = i >> 3, nb = i & 7;
        spin_ge(C_TB + nb, 8);
        gemm_body<0, 0>(g_xh, g_T, nullptr, nullptr, g_G, nullptr,
                        CDIM, CDIM, CDIM, CDIM, gb * 128, nb * 128, sb);
        signal(C_GDONE + gb);
    } else if (b < 432) {                // c[n] = dot(xh[n], u)
        const int i = b - 400;
        spin_ge(C_U, 8);
        gemv_body(g_xh, g_u, nullptr, g_c, i * NTHR);
        signal(C_C);
    } else if (b < 1456) {               // S = G x^T (fp32)
        const int i = b - 432, mb = i >> 5, nb = i & 31;
        spin_ge(C_GDONE + mb, 8);
        gemm_body<0, 1>(g_G, g_xh, nullptr, nullptr, nullptr, g_S,
                        CDIM, CDIM, CDIM, NTOK, mb * 128, nb * 128, sb);
        signal(C_SCNT + mb);
    } else if (b < 1712) {               // softmax(+c)
        const int i = b - 1456, mb = i >> 3, rq = i & 7;
        spin_ge(C_SCNT + mb, 32);
        spin_ge(C_C, 32);
        softmax_body(g_S, g_P, mb * 128 + rq * 16, smem);
        signal(C_PDONE + mb);
    } else if (b < 2736) {               // Y = P x  (split-K x4, fp32 partials)
        const int i = b - 1712, mb = i >> 5, r = i & 31;
        const int nb = r >> 2, ks = r & 3;
        spin_ge(C_PDONE + mb, 8);
        gemm_body<1, 1>(g_P + ks * 1024, g_xh + (size_t)ks * 1024 * CDIM,
                        nullptr, nullptr, nullptr, g_Hp + (size_t)ks * NTOK * CDIM,
                        1024, NTOK, 0, CDIM, mb * 128, nb * 128, sb);
        signal(C_HRDY + mb);
    } else if (b < 2992) {               // reduce
        const int i = b - 2736, mb = i >> 3, rq = i & 7;
        spin_ge(C_HRDY + mb, 32);
        reduce_body(g_Hp, g_H, mb * 128 + rq * 16);
        signal(C_RDONE + mb);
    } else {                             // O = x + Y W2^T + bo2
        const int i = b - 2992, mb = i >> 3, nb = i & 7;
        spin_ge(C_RDONE + mb, 8);
        spin_ge(C_W2B + nb, 8);
        spin_ge(C_OBV, 8);
        gemm_body<0, 2>(g_H, g_W2, g_bo2, a.x, nullptr, a.out,
                        CDIM, CDIM, CDIM, CDIM, mb * 128, nb * 128, sb);
    }
}

// ---------------------------------------------------------------------------
// Fused prep (one launch): counter reset + x/Wq/Wv/Wo converts + Wk transpose.
// Grid: [0,4096) x | [4096,7168) Wq/Wv/Wo | [7168,7424) Wk transpose tiles.
// ---------------------------------------------------------------------------
#define XN4 (NTOK * CDIM / 4)      // 1048576 float4
#define WN4 (CDIM * CDIM / 4)      // 262144 float4

__global__ __launch_bounds__(256) void prep(
    const float4* __restrict__ x,  __half* __restrict__ xh,
    const float4* __restrict__ wq, __half* __restrict__ wqh,
    const float4* __restrict__ wv, __half* __restrict__ wvh,
    const float4* __restrict__ wo, __half* __restrict__ woh,
    const float*  __restrict__ wk, __half* __restrict__ wkT) {
    const int b = blockIdx.x;
    const int t = threadIdx.x;
    if (b == 0) g_cnt[t] = 0;   // reset DAG counters

    if (b < 4096) {                       // x convert
        int k = b * 256 + t;
        float4 v = x[k];
        *(__half2*)(xh + (size_t)k * 4)     = __floats2half2_rn(v.x, v.y);
        *(__half2*)(xh + (size_t)k * 4 + 2) = __floats2half2_rn(v.z, v.w);
    } else if (b < 7168) {                // Wq / Wv / Wo converts
        int j = (b - 4096) * 256 + t;
        int w = j >> 18;                  // / WN4
        int k = j & (WN4 - 1);
        const float4* in = (w == 0) ? wq : (w == 1) ? wv : wo;
        __half* out = (w == 0) ? wqh : (w == 1) ? wvh : woh;
        float4 v = in[k];
        *(__half2*)(out + (size_t)k * 4)     = __floats2half2_rn(v.x, v.y);
        *(__half2*)(out + (size_t)k * 4 + 2) = __floats2half2_rn(v.z, v.w);
    } else {                              // Wk transpose-convert, 64x64 tiles
        __shared__ float s[64][65];
        const int tile = b - 7168;
        const int ti = tile >> 4, tj = tile & 15;
        // load 64x64 fp32 tile (coalesced)
#pragma unroll
        for (int i = 0; i < 4; ++i) {
            int id = t + i * 256;
            int rl = id >> 4, cq = (id & 15) * 4;
            float4 v = *(const float4*)&wk[(size_t)(ti * 64 + rl) * CDIM + tj * 64 + cq];
            s[rl][cq] = v.x; s[rl][cq + 1] = v.y; s[rl][cq + 2] = v.z; s[rl][cq + 3] = v.w;
        }
        __syncthreads();
        // write transposed fp16, 8 contiguous halves per uint4 store
#pragma unroll
        for (int i = 0; i < 2; ++i) {
            int id = t + i * 256;
            int rr = id >> 3, qq = id & 7;
            __half h[8];
#pragma unroll
            for (int j = 0; j < 8; ++j) h[j] = __float2half_rn(s[qq * 8 + j][rr]);
            *(uint4*)&wkT[(size_t)(tj * 64 + rr) * CDIM + ti * 64 + qq * 8] = *(uint4*)h;
        }
    }
}
#define PREP_GRID 7424

// ---------------------------------------------------------------------------
// Launch
// ---------------------------------------------------------------------------
static void* sym(const void* s) { void* p; cudaGetSymbolAddress(&p, s); return p; }

extern "C" void kernel_launch(void* const* d_in, const int* in_sizes, int n_in,
                              void* d_out, int out_size) {
    const float* x  = (const float*)d_in[0];
    const float* Wq = (const float*)d_in[1];
    const float* bq = (const float*)d_in[2];
    const float* Wk = (const float*)d_in[3];
    const float* Wv = (const float*)d_in[5];
    const float* bv = (const float*)d_in[6];
    const float* Wo = (const float*)d_in[7];
    const float* bo = (const float*)d_in[8];
    float* out = (float*)d_out;

    __half* xh  = (__half*)sym(g_xh);
    __half* Wqh = (__half*)sym(g_Wqh);
    __half* WkT = (__half*)sym(g_WkT);
    __half* Wvh = (__half*)sym(g_Wvh);
    __half* Woh = (__half*)sym(g_Woh);

    cudaFuncSetAttribute(mega, cudaFuncAttributeMaxDynamicSharedMemorySize, SMEM_TOTAL);

    // prep: converts + Wk transpose + counter reset (one launch)
    prep<<<PREP_GRID, 256>>>((const float4*)x, xh, (const float4*)Wq, Wqh,
                             (const float4*)Wv, Wvh, (const float4*)Wo, Woh,
                             Wk, WkT);

    // everything else: one DAG-scheduled launch
    MegaArgs ma;
    ma.x = x; ma.bq = bq; ma.bv = bv; ma.bo = bo; ma.out = out;
    mega<<<MEGA_GRID, NTHR, SMEM_TOTAL>>>(ma);
}